// round 8
// baseline (speedup 1.0000x reference)
#include <cuda_runtime.h>

#define NCTA 128
#define TPB  256

// Persistent global state (statically zero-initialized; the end-of-kernel
// done-protocol returns every group counter to 0, so graph replays are fine).
__device__ float g_h0[2 * 128 * 256];
__device__ float g_h1[2 * 128 * 256];
__device__ unsigned g_grp[8];

typedef unsigned long long u64;

__device__ __forceinline__ void fma2(u64 &d, u64 a, u64 b) {
    asm("fma.rn.f32x2 %0, %1, %2, %0;" : "+l"(d) : "l"(a), "l"(b));
}
__device__ __forceinline__ void add2(u64 &d, u64 a) {
    asm("add.rn.f32x2 %0, %0, %1;" : "+l"(d) : "l"(a));
}
__device__ __forceinline__ float hsum(u64 a) {
    union { u64 u; float2 f; } x; x.u = a; return x.f.x + x.f.y;
}
__device__ __forceinline__ float sigm(float x) {
    return __fdividef(1.f, 1.f + __expf(-x));
}

__device__ __forceinline__ void grp_arrive(int bg) {
    asm volatile("red.release.gpu.global.add.u32 [%0], %1;"
                 :: "l"(&g_grp[bg]), "r"(1u) : "memory");
}
__device__ __forceinline__ void grp_wait(int bg, unsigned target) {
    unsigned v;
    do {
        asm volatile("ld.acquire.gpu.global.u32 %0, [%1];"
                     : "=r"(v) : "l"(&g_grp[bg]) : "memory");
    } while (v < target);
}
// Group barrier over the 16 CTAs sharing bg. bar.sync orders all CTA threads'
// prior stores before tid0's release-arrive; ld.acquire + trailing bar.sync
// publishes them to every thread of every waiting CTA.
__device__ __forceinline__ void groupbar(int bg, unsigned target) {
    __syncthreads();
    if (threadIdx.x == 0) {
        grp_arrive(bg);
        grp_wait(bg, target);
    }
    __syncthreads();
}

extern __shared__ float sm[];

__global__ __launch_bounds__(TPB, 1)
void regime_kernel(const float *__restrict__ X,    const float *__restrict__ vix,
                   const float *__restrict__ Wih0, const float *__restrict__ Whh0,
                   const float *__restrict__ bih0, const float *__restrict__ bhh0,
                   const float *__restrict__ Wih1, const float *__restrict__ Whh1,
                   const float *__restrict__ bih1, const float *__restrict__ bhh1,
                   const float *__restrict__ lng,  const float *__restrict__ lnb,
                   const float *__restrict__ lw,   const float *__restrict__ lb,
                   const float *__restrict__ rbud, float *__restrict__ out)
{
    float *W0  = sm;                 // 64 rows x 256, swizzled
    float *W1i = sm + 16384;
    float *W1h = sm + 32768;
    float *h0t = sm + 49152;         // 16 x 256
    float *h1t = sm + 53248;         // 16 x 256
    float *xt  = sm + 57344;         // 16 x 16

    const int t    = threadIdx.x;
    const int bid  = blockIdx.x;
    const int hg   = bid & 15;       // hidden group (16 cols)
    const int bg   = bid >> 4;       // batch group (16 rows)
    const int jg   = t & 63;         // (j,gate): jg = 4*j + g
    const int bh   = t >> 6;         // batch quad id (4 batches each)
    const int g    = jg & 3;
    const int j    = jg >> 2;
    const int rot  = jg & 7;
    const int lane = t & 31;
    const int base = lane & ~3;
    const int R    = g * 256 + hg * 16 + j;   // global gate-row

    // ---- load CTA weight slices into smem, XOR-16B swizzled by row ----
    for (int idx = t; idx < 4096; idx += TPB) {
        int rjg = idx >> 6, q = idx & 63;
        int rr = (rjg & 3) * 256 + hg * 16 + (rjg >> 2);
        int ds = rjg * 256 + ((q ^ (rjg & 7)) << 2);
        *(float4 *)(W0  + ds) = __ldg((const float4 *)(Whh0 + rr * 256 + q * 4));
        *(float4 *)(W1i + ds) = __ldg((const float4 *)(Wih1 + rr * 256 + q * 4));
        *(float4 *)(W1h + ds) = __ldg((const float4 *)(Whh1 + rr * 256 + q * 4));
    }
    // per-thread input weights + fused biases
    float wx[16];
#pragma unroll
    for (int i = 0; i < 16; i += 4) {
        float4 v = __ldg((const float4 *)(Wih0 + R * 16 + i));
        wx[i] = v.x; wx[i + 1] = v.y; wx[i + 2] = v.z; wx[i + 3] = v.w;
    }
    const float b0 = bih0[R] + bhh0[R];
    const float b1 = bih1[R] + bhh1[R];

    float c0[4] = {0, 0, 0, 0}, c1[4] = {0, 0, 0, 0};

    const ulonglong2 *w0p = (const ulonglong2 *)(W0  + jg * 256);
    const ulonglong2 *wip = (const ulonglong2 *)(W1i + jg * 256);
    const ulonglong2 *whp = (const ulonglong2 *)(W1h + jg * 256);
    const ulonglong2 *h0r0 = (const ulonglong2 *)(h0t + (bh * 4 + 0) * 256);
    const ulonglong2 *h0r1 = (const ulonglong2 *)(h0t + (bh * 4 + 1) * 256);
    const ulonglong2 *h0r2 = (const ulonglong2 *)(h0t + (bh * 4 + 2) * 256);
    const ulonglong2 *h0r3 = (const ulonglong2 *)(h0t + (bh * 4 + 3) * 256);
    const ulonglong2 *h1r0 = (const ulonglong2 *)(h1t + (bh * 4 + 0) * 256);
    const ulonglong2 *h1r1 = (const ulonglong2 *)(h1t + (bh * 4 + 1) * 256);
    const ulonglong2 *h1r2 = (const ulonglong2 *)(h1t + (bh * 4 + 2) * 256);
    const ulonglong2 *h1r3 = (const ulonglong2 *)(h1t + (bh * 4 + 3) * 256);

    // ---- main pipelined recurrence: iter k does layer0 step k + layer1 step k-1 ----
    for (int k = 0; k <= 1024; k++) {
        const int pp = (k - 1) & 1;                    // read parity
        // X load first (independent of the h exchange -> overlaps L2 latency)
        if (k < 1024 && t < 64) {
            int bl = t >> 2, i4 = t & 3;
            ((float4 *)xt)[t] =
                __ldg((const float4 *)(X + ((bg * 16 + bl) * 1024 + k) * 16 + i4 * 4));
        }
        if (k == 0) {
            for (int f4 = t; f4 < 1024; f4 += TPB)
                ((float4 *)h0t)[f4] = make_float4(0, 0, 0, 0);
        } else {
            const float4 *src = (const float4 *)(g_h0 + pp * 32768 + bg * 4096);
            for (int f4 = t; f4 < 1024; f4 += TPB)
                ((float4 *)h0t)[f4] = __ldcg(src + f4);
        }
        if (k <= 1) {
            for (int f4 = t; f4 < 1024; f4 += TPB)
                ((float4 *)h1t)[f4] = make_float4(0, 0, 0, 0);
        } else {
            const float4 *src = (const float4 *)(g_h1 + pp * 32768 + bg * 4096);
            for (int f4 = t; f4 < 1024; f4 += TPB)
                ((float4 *)h1t)[f4] = __ldcg(src + f4);
        }
        __syncthreads();

        u64 a0[4] = {0, 0, 0, 0}, aA[4] = {0, 0, 0, 0}, aB[4] = {0, 0, 0, 0};
#pragma unroll 8
        for (int q = 0; q < 64; q++) {
            const int pq = q ^ rot;
            ulonglong2 w0 = w0p[pq];
            ulonglong2 wi = wip[pq];
            ulonglong2 wh = whp[pq];
            ulonglong2 h, z;
            h = h0r0[q]; z = h1r0[q];
            fma2(a0[0], w0.x, h.x); fma2(a0[0], w0.y, h.y);
            fma2(aA[0], wi.x, h.x); fma2(aA[0], wi.y, h.y);
            fma2(aB[0], wh.x, z.x); fma2(aB[0], wh.y, z.y);
            h = h0r1[q]; z = h1r1[q];
            fma2(a0[1], w0.x, h.x); fma2(a0[1], w0.y, h.y);
            fma2(aA[1], wi.x, h.x); fma2(aA[1], wi.y, h.y);
            fma2(aB[1], wh.x, z.x); fma2(aB[1], wh.y, z.y);
            h = h0r2[q]; z = h1r2[q];
            fma2(a0[2], w0.x, h.x); fma2(a0[2], w0.y, h.y);
            fma2(aA[2], wi.x, h.x); fma2(aA[2], wi.y, h.y);
            fma2(aB[2], wh.x, z.x); fma2(aB[2], wh.y, z.y);
            h = h0r3[q]; z = h1r3[q];
            fma2(a0[3], w0.x, h.x); fma2(a0[3], w0.y, h.y);
            fma2(aA[3], wi.x, h.x); fma2(aA[3], wi.y, h.y);
            fma2(aB[3], wh.x, z.x); fma2(aB[3], wh.y, z.y);
        }

        if (k < 1024) {                      // layer-0 step k
#pragma unroll
            for (int bi = 0; bi < 4; bi++) {
                const float4 *xr = (const float4 *)(xt + (bh * 4 + bi) * 16);
                float xc = 0.f;
#pragma unroll
                for (int i4 = 0; i4 < 4; i4++) {
                    float4 xv = xr[i4];
                    xc += wx[i4 * 4 + 0] * xv.x + wx[i4 * 4 + 1] * xv.y +
                          wx[i4 * 4 + 2] * xv.z + wx[i4 * 4 + 3] * xv.w;
                }
                float v = hsum(a0[bi]) + b0 + xc;
                v = (g == 2) ? tanhf(v) : sigm(v);
                float iv = __shfl_sync(0xffffffffu, v, base);
                float fv = __shfl_sync(0xffffffffu, v, base + 1);
                float gv = __shfl_sync(0xffffffffu, v, base + 2);
                float ov = __shfl_sync(0xffffffffu, v, base + 3);
                if (g == 0) {
                    c0[bi] = fv * c0[bi] + iv * gv;
                    float hh = ov * tanhf(c0[bi]);
                    __stcg(g_h0 + (k & 1) * 32768 +
                           (bg * 16 + bh * 4 + bi) * 256 + hg * 16 + j, hh);
                }
            }
        }
        if (k >= 1) {                        // layer-1 step k-1
#pragma unroll
            for (int bi = 0; bi < 4; bi++) {
                float v = hsum(aA[bi]) + hsum(aB[bi]) + b1;
                v = (g == 2) ? tanhf(v) : sigm(v);
                float iv = __shfl_sync(0xffffffffu, v, base);
                float fv = __shfl_sync(0xffffffffu, v, base + 1);
                float gv = __shfl_sync(0xffffffffu, v, base + 2);
                float ov = __shfl_sync(0xffffffffu, v, base + 3);
                if (g == 0) {
                    c1[bi] = fv * c1[bi] + iv * gv;
                    float hh = ov * tanhf(c1[bi]);
                    __stcg(g_h1 + (k & 1) * 32768 +
                           (bg * 16 + bh * 4 + bi) * 256 + hg * 16 + j, hh);
                }
            }
        }
        // per-group (16 CTA) barrier — replaces threadfence + global barrier
        groupbar(bg, 16u * (unsigned)(k + 1));
    }

    // ---- done-pass: one extra arrive per CTA so the group leader can safely
    //      reset the monotonic counter for the next graph replay. ----
    if (t == 0) grp_arrive(bg);

    // ---- head: group-leader CTA (hg==0) handles its own 16 batches; their
    //      h1 data is complete as of this group's final barrier. h_last lives
    //      at parity (1024&1)=0 of g_h1. ----
    if (hg == 0) {
        if (t < 16) {
            const int b = bg * 16 + t;
            const float *h = g_h1 + b * 256;
            float s = 0.f, s2 = 0.f;
            for (int i = 0; i < 256; i++) { float v = __ldcg(h + i); s += v; s2 += v * v; }
            float mu  = s * (1.f / 256.f);
            float var = s2 * (1.f / 256.f) - mu * mu;
            float inv = rsqrtf(var + 1e-5f);
            float l0 = lb[0], l1 = lb[1], l2 = lb[2];
            for (int i = 0; i < 256; i++) {
                float v  = __ldcg(h + i);
                float hn = (v - mu) * inv * lng[i] + lnb[i];
                l0 += hn * lw[i]; l1 += hn * lw[256 + i]; l2 += hn * lw[512 + i];
            }
            float m  = fmaxf(l0, fmaxf(l1, l2));
            float e0 = __expf(l0 - m), e1 = __expf(l1 - m), e2 = __expf(l2 - m);
            float es = e0 + e1 + e2;
            float p0 = e0 / es, p1 = e1 / es, p2 = e2 / es;

            float bm[3], bs[3];
#pragma unroll
            for (int r = 0; r < 3; r++) {
                float mm = -1e30f;
                for (int p = 0; p < 32; p++) mm = fmaxf(mm, rbud[r * 32 + p]);
                float ss = 0.f;
                for (int p = 0; p < 32; p++) ss += __expf(rbud[r * 32 + p] - mm);
                bm[r] = mm; bs[r] = ss;
            }
            float w0s = p0 / bs[0], w1s = p1 / bs[1], w2s = p2 / bs[2];
            float bb[32];
            float eqs = 0.f, dfs = 0.f;
            for (int p = 0; p < 32; p++) {
                float v = w0s * __expf(rbud[p]      - bm[0]) +
                          w1s * __expf(rbud[32 + p] - bm[1]) +
                          w2s * __expf(rbud[64 + p] - bm[2]);
                bb[p] = v;
                if (p < 24) eqs += v; else dfs += v;
            }
            bool  mask      = vix[b] >= 30.0f;
            float shortfall = 0.4f - dfs;
            float ratio     = fminf(shortfall / fmaxf(eqs, 1e-8f), 0.8f);
            bool  apply     = mask && (shortfall > 0.f) && (eqs > 1e-8f);
            float bsel[32], bsum = 0.f;
            for (int p = 0; p < 32; p++) {
                float b2 = (p < 24) ? bb[p] * (1.f - ratio) : bb[p] + shortfall * (1.f / 8.f);
                float v  = apply ? b2 : bb[p];
                bsel[p] = v; bsum += v;
            }
            float innorm = 1.f / (bsum + 1e-8f);
            for (int p = 0; p < 32; p++)
                out[b * 32 + p] = mask ? bsel[p] * innorm : bb[p];
            out[4096 + b * 3 + 0] = p0;
            out[4096 + b * 3 + 1] = p1;
            out[4096 + b * 3 + 2] = p2;
        }
        // reset the group counter once ALL 16 group CTAs have done-arrived
        // (count reaches 16*1025 + 16 = 16*1026). Safe for graph replay.
        if (t == 0) {
            grp_wait(bg, 16u * 1026u);
            asm volatile("st.relaxed.gpu.global.u32 [%0], %1;"
                         :: "l"(&g_grp[bg]), "r"(0u) : "memory");
        }
    }
}

extern "C" void kernel_launch(void *const *d_in, const int *in_sizes, int n_in,
                              void *d_out, int out_size)
{
    (void)in_sizes; (void)n_in; (void)out_size;
    static int smem_set = 0;
    const int smem = 57600 * 4;   // 230400 B
    if (!smem_set) {
        cudaFuncSetAttribute(regime_kernel,
                             cudaFuncAttributeMaxDynamicSharedMemorySize, smem);
        smem_set = 1;
    }
    regime_kernel<<<NCTA, TPB, smem>>>(
        (const float *)d_in[0],  (const float *)d_in[1],  (const float *)d_in[2],
        (const float *)d_in[3],  (const float *)d_in[4],  (const float *)d_in[5],
        (const float *)d_in[6],  (const float *)d_in[7],  (const float *)d_in[8],
        (const float *)d_in[9],  (const float *)d_in[10], (const float *)d_in[11],
        (const float *)d_in[12], (const float *)d_in[13], (const float *)d_in[14],
        (float *)d_out);
}

// round 9
// speedup vs baseline: 1.5957x; 1.5957x over previous
#include <cuda_runtime.h>

#define NCTA 128
#define TPB  256

// Persistent global state (statically zero-initialized; the end-of-kernel
// done-protocol returns every group counter to 0, so graph replays are fine).
__device__ float g_h0[2 * 128 * 256];
__device__ float g_h1[2 * 128 * 256];
__device__ unsigned g_grp[8];

typedef unsigned long long u64;

__device__ __forceinline__ void fma2(u64 &d, u64 a, u64 b) {
    asm("fma.rn.f32x2 %0, %1, %2, %0;" : "+l"(d) : "l"(a), "l"(b));
}
__device__ __forceinline__ float hsum(u64 a) {
    union { u64 u; float2 f; } x; x.u = a; return x.f.x + x.f.y;
}
__device__ __forceinline__ float sigm(float x) {
    return __fdividef(1.f, 1.f + __expf(-x));
}
// fast, accurate tanh (no libdevice branches): 2/(1+e^{-2x}) - 1
__device__ __forceinline__ float tanha(float x) {
    return __fdividef(2.f, 1.f + __expf(-2.f * x)) - 1.f;
}

__device__ __forceinline__ void grp_arrive(int bg) {
    asm volatile("red.release.gpu.global.add.u32 [%0], %1;"
                 :: "l"(&g_grp[bg]), "r"(1u) : "memory");
}
__device__ __forceinline__ void grp_wait(int bg, unsigned target) {
    unsigned v, ns = 32;
    for (;;) {
        asm volatile("ld.acquire.gpu.global.u32 %0, [%1];"
                     : "=r"(v) : "l"(&g_grp[bg]) : "memory");
        if (v >= target) break;
        __nanosleep(ns);                 // backoff: avoid thrashing the LTS line
        if (ns < 256) ns <<= 1;
    }
}
// Group barrier over the 16 CTAs sharing bg. bar.sync orders all CTA threads'
// prior stores before tid0's release-arrive; ld.acquire + trailing bar.sync
// publishes them to every thread of every waiting CTA.
__device__ __forceinline__ void groupbar(int bg, unsigned target) {
    __syncthreads();
    if (threadIdx.x == 0) {
        grp_arrive(bg);
        grp_wait(bg, target);
    }
    __syncthreads();
}

extern __shared__ float sm[];

__global__ __launch_bounds__(TPB, 1)
void regime_kernel(const float *__restrict__ X,    const float *__restrict__ vix,
                   const float *__restrict__ Wih0, const float *__restrict__ Whh0,
                   const float *__restrict__ bih0, const float *__restrict__ bhh0,
                   const float *__restrict__ Wih1, const float *__restrict__ Whh1,
                   const float *__restrict__ bih1, const float *__restrict__ bhh1,
                   const float *__restrict__ lng,  const float *__restrict__ lnb,
                   const float *__restrict__ lw,   const float *__restrict__ lb,
                   const float *__restrict__ rbud, float *__restrict__ out)
{
    float *W0  = sm;                 // 64 rows x 256, swizzled
    float *W1i = sm + 16384;
    float *W1h = sm + 32768;
    float *h0t = sm + 49152;         // 16 x 256
    float *h1t = sm + 53248;         // 16 x 256
    float *xt  = sm + 57344;         // 16 x 16

    const int t    = threadIdx.x;
    const int bid  = blockIdx.x;
    const int hg   = bid & 15;       // hidden group (16 cols)
    const int bg   = bid >> 4;       // batch group (16 rows)
    const int jg   = t & 63;         // (j,gate): jg = 4*j + g
    const int bh   = t >> 6;         // batch quad id (4 batches each)
    const int g    = jg & 3;
    const int j    = jg >> 2;
    const int rot  = jg & 7;
    const int lane = t & 31;
    const int base = lane & ~3;
    const int R    = g * 256 + hg * 16 + j;   // global gate-row

    // ---- load CTA weight slices into smem, XOR-16B swizzled by row ----
    for (int idx = t; idx < 4096; idx += TPB) {
        int rjg = idx >> 6, q = idx & 63;
        int rr = (rjg & 3) * 256 + hg * 16 + (rjg >> 2);
        int ds = rjg * 256 + ((q ^ (rjg & 7)) << 2);
        *(float4 *)(W0  + ds) = __ldg((const float4 *)(Whh0 + rr * 256 + q * 4));
        *(float4 *)(W1i + ds) = __ldg((const float4 *)(Wih1 + rr * 256 + q * 4));
        *(float4 *)(W1h + ds) = __ldg((const float4 *)(Whh1 + rr * 256 + q * 4));
    }
    // per-thread input weights + fused biases
    float wx[16];
#pragma unroll
    for (int i = 0; i < 16; i += 4) {
        float4 v = __ldg((const float4 *)(Wih0 + R * 16 + i));
        wx[i] = v.x; wx[i + 1] = v.y; wx[i + 2] = v.z; wx[i + 3] = v.w;
    }
    const float b0 = bih0[R] + bhh0[R];
    const float b1 = bih1[R] + bhh1[R];

    float c0[4] = {0, 0, 0, 0}, c1[4] = {0, 0, 0, 0};

    const ulonglong2 *w0p = (const ulonglong2 *)(W0  + jg * 256);
    const ulonglong2 *wip = (const ulonglong2 *)(W1i + jg * 256);
    const ulonglong2 *whp = (const ulonglong2 *)(W1h + jg * 256);
    const ulonglong2 *h0r0 = (const ulonglong2 *)(h0t + (bh * 4 + 0) * 256);
    const ulonglong2 *h0r1 = (const ulonglong2 *)(h0t + (bh * 4 + 1) * 256);
    const ulonglong2 *h0r2 = (const ulonglong2 *)(h0t + (bh * 4 + 2) * 256);
    const ulonglong2 *h0r3 = (const ulonglong2 *)(h0t + (bh * 4 + 3) * 256);
    const ulonglong2 *h1r0 = (const ulonglong2 *)(h1t + (bh * 4 + 0) * 256);
    const ulonglong2 *h1r1 = (const ulonglong2 *)(h1t + (bh * 4 + 1) * 256);
    const ulonglong2 *h1r2 = (const ulonglong2 *)(h1t + (bh * 4 + 2) * 256);
    const ulonglong2 *h1r3 = (const ulonglong2 *)(h1t + (bh * 4 + 3) * 256);

    // ---- main pipelined recurrence: iter k does layer0 step k + layer1 step k-1 ----
    for (int k = 0; k <= 1024; k++) {
        const int pp = (k - 1) & 1;                    // read parity
        // X load first (independent of the h exchange -> overlaps L2 latency)
        if (k < 1024 && t < 64) {
            int bl = t >> 2, i4 = t & 3;
            ((float4 *)xt)[t] =
                __ldg((const float4 *)(X + ((bg * 16 + bl) * 1024 + k) * 16 + i4 * 4));
        }
        if (k == 0) {
            for (int f4 = t; f4 < 1024; f4 += TPB)
                ((float4 *)h0t)[f4] = make_float4(0, 0, 0, 0);
        } else {
            const float4 *src = (const float4 *)(g_h0 + pp * 32768 + bg * 4096);
            for (int f4 = t; f4 < 1024; f4 += TPB)
                ((float4 *)h0t)[f4] = __ldcg(src + f4);
        }
        if (k <= 1) {
            for (int f4 = t; f4 < 1024; f4 += TPB)
                ((float4 *)h1t)[f4] = make_float4(0, 0, 0, 0);
        } else {
            const float4 *src = (const float4 *)(g_h1 + pp * 32768 + bg * 4096);
            for (int f4 = t; f4 < 1024; f4 += TPB)
                ((float4 *)h1t)[f4] = __ldcg(src + f4);
        }
        __syncthreads();

        u64 a0[4] = {0, 0, 0, 0}, aA[4] = {0, 0, 0, 0}, aB[4] = {0, 0, 0, 0};
#pragma unroll 8
        for (int q = 0; q < 64; q++) {
            const int pq = q ^ rot;
            ulonglong2 w0 = w0p[pq];
            ulonglong2 wi = wip[pq];
            ulonglong2 wh = whp[pq];
            ulonglong2 h, z;
            h = h0r0[q]; z = h1r0[q];
            fma2(a0[0], w0.x, h.x); fma2(a0[0], w0.y, h.y);
            fma2(aA[0], wi.x, h.x); fma2(aA[0], wi.y, h.y);
            fma2(aB[0], wh.x, z.x); fma2(aB[0], wh.y, z.y);
            h = h0r1[q]; z = h1r1[q];
            fma2(a0[1], w0.x, h.x); fma2(a0[1], w0.y, h.y);
            fma2(aA[1], wi.x, h.x); fma2(aA[1], wi.y, h.y);
            fma2(aB[1], wh.x, z.x); fma2(aB[1], wh.y, z.y);
            h = h0r2[q]; z = h1r2[q];
            fma2(a0[2], w0.x, h.x); fma2(a0[2], w0.y, h.y);
            fma2(aA[2], wi.x, h.x); fma2(aA[2], wi.y, h.y);
            fma2(aB[2], wh.x, z.x); fma2(aB[2], wh.y, z.y);
            h = h0r3[q]; z = h1r3[q];
            fma2(a0[3], w0.x, h.x); fma2(a0[3], w0.y, h.y);
            fma2(aA[3], wi.x, h.x); fma2(aA[3], wi.y, h.y);
            fma2(aB[3], wh.x, z.x); fma2(aB[3], wh.y, z.y);
        }

        if (k < 1024) {                      // layer-0 step k
#pragma unroll
            for (int bi = 0; bi < 4; bi++) {
                const float4 *xr = (const float4 *)(xt + (bh * 4 + bi) * 16);
                float xc = 0.f;
#pragma unroll
                for (int i4 = 0; i4 < 4; i4++) {
                    float4 xv = xr[i4];
                    xc += wx[i4 * 4 + 0] * xv.x + wx[i4 * 4 + 1] * xv.y +
                          wx[i4 * 4 + 2] * xv.z + wx[i4 * 4 + 3] * xv.w;
                }
                float v = hsum(a0[bi]) + b0 + xc;
                v = (g == 2) ? tanha(v) : sigm(v);
                float iv = __shfl_sync(0xffffffffu, v, base);
                float fv = __shfl_sync(0xffffffffu, v, base + 1);
                float gv = __shfl_sync(0xffffffffu, v, base + 2);
                float ov = __shfl_sync(0xffffffffu, v, base + 3);
                if (g == 0) {
                    c0[bi] = fv * c0[bi] + iv * gv;
                    float hh = ov * tanha(c0[bi]);
                    __stcg(g_h0 + (k & 1) * 32768 +
                           (bg * 16 + bh * 4 + bi) * 256 + hg * 16 + j, hh);
                }
            }
        }
        if (k >= 1) {                        // layer-1 step k-1
#pragma unroll
            for (int bi = 0; bi < 4; bi++) {
                float v = hsum(aA[bi]) + hsum(aB[bi]) + b1;
                v = (g == 2) ? tanha(v) : sigm(v);
                float iv = __shfl_sync(0xffffffffu, v, base);
                float fv = __shfl_sync(0xffffffffu, v, base + 1);
                float gv = __shfl_sync(0xffffffffu, v, base + 2);
                float ov = __shfl_sync(0xffffffffu, v, base + 3);
                if (g == 0) {
                    c1[bi] = fv * c1[bi] + iv * gv;
                    float hh = ov * tanha(c1[bi]);
                    __stcg(g_h1 + (k & 1) * 32768 +
                           (bg * 16 + bh * 4 + bi) * 256 + hg * 16 + j, hh);
                }
            }
        }
        // per-group (16 CTA) barrier
        groupbar(bg, 16u * (unsigned)(k + 1));
    }

    // ---- done-pass: one extra arrive per CTA so the group leader can safely
    //      reset the monotonic counter for the next graph replay. ----
    if (t == 0) grp_arrive(bg);

    // ---- head: group-leader CTA (hg==0) handles its own 16 batches; their
    //      h1 data is complete as of this group's final barrier. h_last lives
    //      at parity (1024&1)=0 of g_h1. ----
    if (hg == 0) {
        if (t < 16) {
            const int b = bg * 16 + t;
            const float *h = g_h1 + b * 256;
            float s = 0.f, s2 = 0.f;
            for (int i = 0; i < 256; i++) { float v = __ldcg(h + i); s += v; s2 += v * v; }
            float mu  = s * (1.f / 256.f);
            float var = s2 * (1.f / 256.f) - mu * mu;
            float inv = rsqrtf(var + 1e-5f);
            float l0 = lb[0], l1 = lb[1], l2 = lb[2];
            for (int i = 0; i < 256; i++) {
                float v  = __ldcg(h + i);
                float hn = (v - mu) * inv * lng[i] + lnb[i];
                l0 += hn * lw[i]; l1 += hn * lw[256 + i]; l2 += hn * lw[512 + i];
            }
            float m  = fmaxf(l0, fmaxf(l1, l2));
            float e0 = __expf(l0 - m), e1 = __expf(l1 - m), e2 = __expf(l2 - m);
            float es = e0 + e1 + e2;
            float p0 = e0 / es, p1 = e1 / es, p2 = e2 / es;

            float bm[3], bs[3];
#pragma unroll
            for (int r = 0; r < 3; r++) {
                float mm = -1e30f;
                for (int p = 0; p < 32; p++) mm = fmaxf(mm, rbud[r * 32 + p]);
                float ss = 0.f;
                for (int p = 0; p < 32; p++) ss += __expf(rbud[r * 32 + p] - mm);
                bm[r] = mm; bs[r] = ss;
            }
            float w0s = p0 / bs[0], w1s = p1 / bs[1], w2s = p2 / bs[2];
            float bb[32];
            float eqs = 0.f, dfs = 0.f;
            for (int p = 0; p < 32; p++) {
                float v = w0s * __expf(rbud[p]      - bm[0]) +
                          w1s * __expf(rbud[32 + p] - bm[1]) +
                          w2s * __expf(rbud[64 + p] - bm[2]);
                bb[p] = v;
                if (p < 24) eqs += v; else dfs += v;
            }
            bool  mask      = vix[b] >= 30.0f;
            float shortfall = 0.4f - dfs;
            float ratio     = fminf(shortfall / fmaxf(eqs, 1e-8f), 0.8f);
            bool  apply     = mask && (shortfall > 0.f) && (eqs > 1e-8f);
            float bsel[32], bsum = 0.f;
            for (int p = 0; p < 32; p++) {
                float b2 = (p < 24) ? bb[p] * (1.f - ratio) : bb[p] + shortfall * (1.f / 8.f);
                float v  = apply ? b2 : bb[p];
                bsel[p] = v; bsum += v;
            }
            float innorm = 1.f / (bsum + 1e-8f);
            for (int p = 0; p < 32; p++)
                out[b * 32 + p] = mask ? bsel[p] * innorm : bb[p];
            out[4096 + b * 3 + 0] = p0;
            out[4096 + b * 3 + 1] = p1;
            out[4096 + b * 3 + 2] = p2;
        }
        // reset the group counter once ALL 16 group CTAs have done-arrived
        // (count reaches 16*1025 + 16 = 16*1026). Safe for graph replay.
        if (t == 0) {
            grp_wait(bg, 16u * 1026u);
            asm volatile("st.relaxed.gpu.global.u32 [%0], %1;"
                         :: "l"(&g_grp[bg]), "r"(0u) : "memory");
        }
    }
}

extern "C" void kernel_launch(void *const *d_in, const int *in_sizes, int n_in,
                              void *d_out, int out_size)
{
    (void)in_sizes; (void)n_in; (void)out_size;
    static int smem_set = 0;
    const int smem = 57600 * 4;   // 230400 B
    if (!smem_set) {
        cudaFuncSetAttribute(regime_kernel,
                             cudaFuncAttributeMaxDynamicSharedMemorySize, smem);
        smem_set = 1;
    }
    regime_kernel<<<NCTA, TPB, smem>>>(
        (const float *)d_in[0],  (const float *)d_in[1],  (const float *)d_in[2],
        (const float *)d_in[3],  (const float *)d_in[4],  (const float *)d_in[5],
        (const float *)d_in[6],  (const float *)d_in[7],  (const float *)d_in[8],
        (const float *)d_in[9],  (const float *)d_in[10], (const float *)d_in[11],
        (const float *)d_in[12], (const float *)d_in[13], (const float *)d_in[14],
        (float *)d_out);
}